// round 2
// baseline (speedup 1.0000x reference)
#include <cuda_runtime.h>
#include <math.h>

#define S_TOK  8192
#define HID    1024
#define NH     16
#define NKV    8
#define HD     128
#define SEGLEN 1024
#define QD     (NH * HD)   // 2048
#define KD     (NKV * HD)  // 1024
#define SCALE  0.08838834764831845f

typedef unsigned long long u64;

__device__ __forceinline__ u64 pack2(float a, float b) {
    u64 r; asm("mov.b64 %0,{%1,%2};" : "=l"(r) : "f"(a), "f"(b)); return r;
}
__device__ __forceinline__ void unpack2(u64 v, float& a, float& b) {
    asm("mov.b64 {%0,%1},%2;" : "=f"(a), "=f"(b) : "l"(v));
}
__device__ __forceinline__ void fma2(u64& c, u64 a, u64 b) {
    asm("fma.rn.f32x2 %0,%1,%2,%3;" : "=l"(c) : "l"(a), "l"(b), "l"(c));
}
__device__ __forceinline__ u64 mul2(u64 a, u64 b) {
    u64 r; asm("mul.rn.f32x2 %0,%1,%2;" : "=l"(r) : "l"(a), "l"(b)); return r;
}

// Scratch (static device arrays: no allocation in kernel_launch)
__device__ float g_q[S_TOK * QD];   // Q after proj/norm/rope   [S, 2048]
__device__ float g_k[S_TOK * KD];   // K after proj/norm/rope   [S, 1024]
__device__ float g_v[S_TOK * KD];   // V after proj             [S, 1024]
__device__ float g_o[S_TOK * QD];   // attention output         [S, 2048]

// ---------------------------------------------------------------------------
// Generic GEMM: C[M,N] = A[M,K] @ B[N,K]^T   (A row-major, B = weights [N,K])
// 128x128 block tile, BK=16, 256 threads, 8x8 per thread, f32x2 inner loop.
// ---------------------------------------------------------------------------
__global__ __launch_bounds__(256) void gemm_nt(
    const float* __restrict__ A, const float* __restrict__ B,
    float* __restrict__ C, int M, int N, int K)
{
    __shared__ float As[16][132];   // transposed: As[k][m], pad 4
    __shared__ float Bs[16][132];   // transposed: Bs[k][n], pad 4

    const int tid = threadIdx.x;
    const int tx = tid & 15, ty = tid >> 4;
    const int m0 = blockIdx.y << 7, n0 = blockIdx.x << 7;
    const int lrow = tid >> 2, lc4 = tid & 3;

    u64 acc[8][4];
#pragma unroll
    for (int i = 0; i < 8; i++)
#pragma unroll
        for (int j = 0; j < 4; j++) acc[i][j] = 0ULL;

    for (int k0 = 0; k0 < K; k0 += 16) {
#pragma unroll
        for (int it = 0; it < 2; it++) {
            int row = lrow + it * 64;
            float4 va = *(const float4*)(A + (size_t)(m0 + row) * K + k0 + (lc4 << 2));
            As[lc4 * 4 + 0][row] = va.x; As[lc4 * 4 + 1][row] = va.y;
            As[lc4 * 4 + 2][row] = va.z; As[lc4 * 4 + 3][row] = va.w;
            float4 vb = *(const float4*)(B + (size_t)(n0 + row) * K + k0 + (lc4 << 2));
            Bs[lc4 * 4 + 0][row] = vb.x; Bs[lc4 * 4 + 1][row] = vb.y;
            Bs[lc4 * 4 + 2][row] = vb.z; Bs[lc4 * 4 + 3][row] = vb.w;
        }
        __syncthreads();
#pragma unroll
        for (int kk = 0; kk < 16; kk++) {
            float4 a0 = *(const float4*)&As[kk][ty * 8];
            float4 a1 = *(const float4*)&As[kk][ty * 8 + 4];
            const u64* brow = (const u64*)&Bs[kk][tx * 8];
            u64 b0 = brow[0], b1 = brow[1], b2 = brow[2], b3 = brow[3];
            float av[8] = {a0.x, a0.y, a0.z, a0.w, a1.x, a1.y, a1.z, a1.w};
#pragma unroll
            for (int i = 0; i < 8; i++) {
                u64 ad = pack2(av[i], av[i]);
                fma2(acc[i][0], ad, b0);
                fma2(acc[i][1], ad, b1);
                fma2(acc[i][2], ad, b2);
                fma2(acc[i][3], ad, b3);
            }
        }
        __syncthreads();
    }

#pragma unroll
    for (int i = 0; i < 8; i++) {
        float o[8];
#pragma unroll
        for (int j = 0; j < 4; j++) unpack2(acc[i][j], o[2 * j], o[2 * j + 1]);
        float* cp = C + (size_t)(m0 + ty * 8 + i) * N + n0 + tx * 8;
        *(float4*)cp       = make_float4(o[0], o[1], o[2], o[3]);
        *(float4*)(cp + 4) = make_float4(o[4], o[5], o[6], o[7]);
    }
}

// ---------------------------------------------------------------------------
// Fused RMSNorm + multimodal RoPE, in place on g_q / g_k.
// One warp per (token, head) vector of 128 floats; lane owns 4 dims.
// rot(x)[d] = d<64 ? -x[d+64] : x[d-64]  -> partner via shfl_xor(.,16)
// cos_e[d]  = d<64 ? cos[0,s,d] : cos[1,s,d]
// ---------------------------------------------------------------------------
__global__ __launch_bounds__(256) void norm_rope_kernel(
    float* __restrict__ q, float* __restrict__ k,
    const float* __restrict__ cosT, const float* __restrict__ sinT,
    const float* __restrict__ qw, const float* __restrict__ kw)
{
    int gw = (blockIdx.x * blockDim.x + threadIdx.x) >> 5;
    int lane = threadIdx.x & 31;
    if (gw >= S_TOK * (NH + NKV)) return;
    int s = gw / (NH + NKV);
    int h = gw - s * (NH + NKV);

    float* base; const float* w;
    if (h < NH) { base = q + (size_t)s * QD + h * HD;        w = qw; }
    else        { base = k + (size_t)s * KD + (h - NH) * HD; w = kw; }

    float4 x = *(const float4*)(base + lane * 4);
    float ss = x.x * x.x + x.y * x.y + x.z * x.z + x.w * x.w;
#pragma unroll
    for (int m = 16; m > 0; m >>= 1) ss += __shfl_xor_sync(0xffffffffu, ss, m);
    float r = rsqrtf(ss * (1.0f / 128.0f) + 1e-6f);

    float4 wv = *(const float4*)(w + lane * 4);
    float xn0 = x.x * r * wv.x;
    float xn1 = x.y * r * wv.y;
    float xn2 = x.z * r * wv.z;
    float xn3 = x.w * r * wv.w;

    float p0 = __shfl_xor_sync(0xffffffffu, xn0, 16);
    float p1 = __shfl_xor_sync(0xffffffffu, xn1, 16);
    float p2 = __shfl_xor_sync(0xffffffffu, xn2, 16);
    float p3 = __shfl_xor_sync(0xffffffffu, xn3, 16);
    float sgn = (lane < 16) ? -1.0f : 1.0f;

    size_t toff = ((lane < 16) ? (size_t)0 : (size_t)S_TOK * HD)
                + (size_t)s * HD + lane * 4;
    float4 cv = *(const float4*)(cosT + toff);
    float4 sv = *(const float4*)(sinT + toff);

    float4 outv;
    outv.x = xn0 * cv.x + sgn * p0 * sv.x;
    outv.y = xn1 * cv.y + sgn * p1 * sv.y;
    outv.z = xn2 * cv.z + sgn * p2 * sv.z;
    outv.w = xn3 * cv.w + sgn * p3 * sv.w;
    *(float4*)(base + lane * 4) = outv;
}

// ---------------------------------------------------------------------------
// Flash attention over block-diagonal segments.
// Block = (qtile of 64 rows, seg, head). 256 threads (16x16).
// Streams 64-key chunks; online softmax; fp32 f32x2 inner loops.
// K tile XOR-swizzled so the stride-4 row reads are ~2-way conflicted.
// ---------------------------------------------------------------------------
__global__ __launch_bounds__(256) void attn_kernel(
    const float* __restrict__ q, const float* __restrict__ k,
    const float* __restrict__ v, float* __restrict__ o)
{
    extern __shared__ float sm[];
    float* Qs = sm;             // [64][128]
    float* Ks = sm + 8192;      // [64][128]  (swizzled)
    float* Vs = sm + 16384;     // [64][128]
    float* Ps = sm + 24576;     // [64][68]

    const int tid = threadIdx.x;
    const int tx = tid & 15, ty = tid >> 4;
    const int qt = blockIdx.x, seg = blockIdx.y, h = blockIdx.z;
    const int hkv = h >> 1;   // GQA groups = 2

    const float* Qg = q + (size_t)(seg * SEGLEN + qt * 64) * QD + h * HD;
    const float* Kg = k + (size_t)(seg * SEGLEN) * KD + hkv * HD;
    const float* Vg = v + (size_t)(seg * SEGLEN) * KD + hkv * HD;

#pragma unroll
    for (int it = 0; it < 8; it++) {
        int idx = tid + it * 256;
        int r = idx >> 5, d4 = idx & 31;
        *(float4*)&Qs[r * 128 + (d4 << 2)] =
            *(const float4*)(Qg + (size_t)r * QD + (d4 << 2));
    }

    float mrow[4] = {-INFINITY, -INFINITY, -INFINITY, -INFINITY};
    float lrow[4] = {0.f, 0.f, 0.f, 0.f};
    u64 O2[4][4];
#pragma unroll
    for (int i = 0; i < 4; i++)
#pragma unroll
        for (int j = 0; j < 4; j++) O2[i][j] = 0ULL;

    for (int ck = 0; ck < SEGLEN / 64; ck++) {
        __syncthreads();   // previous PV done before overwriting K/V/P
#pragma unroll
        for (int it = 0; it < 8; it++) {
            int idx = tid + it * 256;
            int c = idx >> 5, d4 = idx & 31;
            int sw = d4 ^ ((c >> 2) & 7);
            size_t goff = (size_t)(ck * 64 + c) * KD + (d4 << 2);
            *(float4*)&Ks[c * 128 + (sw << 2)] = *(const float4*)(Kg + goff);
            *(float4*)&Vs[c * 128 + (d4 << 2)] = *(const float4*)(Vg + goff);
        }
        __syncthreads();

        // ---- scores: s[4][4] = Q(rows ty*4..) . K(cols tx*4..) -------------
        u64 sp[4][4];
#pragma unroll
        for (int i = 0; i < 4; i++)
#pragma unroll
            for (int j = 0; j < 4; j++) sp[i][j] = 0ULL;

#pragma unroll 8
        for (int kk4 = 0; kk4 < 32; kk4++) {
            int swk = (kk4 ^ (tx & 7)) << 2;
            u64 qp[4][2], kp[4][2];
#pragma unroll
            for (int i = 0; i < 4; i++) {
                const u64* qr = (const u64*)&Qs[(ty * 4 + i) * 128 + (kk4 << 2)];
                qp[i][0] = qr[0]; qp[i][1] = qr[1];
                const u64* kr = (const u64*)&Ks[(tx * 4 + i) * 128 + swk];
                kp[i][0] = kr[0]; kp[i][1] = kr[1];
            }
#pragma unroll
            for (int i = 0; i < 4; i++)
#pragma unroll
                for (int j = 0; j < 4; j++) {
                    fma2(sp[i][j], qp[i][0], kp[j][0]);
                    fma2(sp[i][j], qp[i][1], kp[j][1]);
                }
        }

        // ---- online softmax -------------------------------------------------
        float pcur[4][4];
#pragma unroll
        for (int i = 0; i < 4; i++) {
            float best = -INFINITY;
#pragma unroll
            for (int j = 0; j < 4; j++) {
                float lo, hi; unpack2(sp[i][j], lo, hi);
                float val = (lo + hi) * SCALE;
                pcur[i][j] = val;
                best = fmaxf(best, val);
            }
#pragma unroll
            for (int msk = 8; msk > 0; msk >>= 1)
                best = fmaxf(best, __shfl_xor_sync(0xffffffffu, best, msk));

            float mnew = fmaxf(mrow[i], best);
            float alpha = __expf(mrow[i] - mnew);
            mrow[i] = mnew;
            float sum = 0.f;
#pragma unroll
            for (int j = 0; j < 4; j++) {
                float e = __expf(pcur[i][j] - mnew);
                pcur[i][j] = e;
                sum += e;
            }
#pragma unroll
            for (int msk = 8; msk > 0; msk >>= 1)
                sum += __shfl_xor_sync(0xffffffffu, sum, msk);
            lrow[i] = lrow[i] * alpha + sum;

            u64 ad = pack2(alpha, alpha);
#pragma unroll
            for (int j = 0; j < 4; j++) O2[i][j] = mul2(O2[i][j], ad);

            *(float4*)&Ps[(ty * 4 + i) * 68 + tx * 4] =
                make_float4(pcur[i][0], pcur[i][1], pcur[i][2], pcur[i][3]);
        }
        __syncthreads();

        // ---- PV: O[rows ty*4..][cols tx*8..] += P @ V -----------------------
#pragma unroll 4
        for (int j4 = 0; j4 < 16; j4++) {
            float4 pv[4];
#pragma unroll
            for (int i = 0; i < 4; i++)
                pv[i] = *(const float4*)&Ps[(ty * 4 + i) * 68 + (j4 << 2)];
#pragma unroll
            for (int e = 0; e < 4; e++) {
                const u64* vr = (const u64*)&Vs[(j4 * 4 + e) * 128 + tx * 8];
                u64 v0 = vr[0], v1 = vr[1], v2 = vr[2], v3 = vr[3];
#pragma unroll
                for (int i = 0; i < 4; i++) {
                    float pe = ((const float*)&pv[i])[e];
                    u64 pd = pack2(pe, pe);
                    fma2(O2[i][0], pd, v0);
                    fma2(O2[i][1], pd, v1);
                    fma2(O2[i][2], pd, v2);
                    fma2(O2[i][3], pd, v3);
                }
            }
        }
    }

    // ---- normalize + write ---------------------------------------------------
    float* Og = o + (size_t)(seg * SEGLEN + qt * 64) * QD + h * HD;
#pragma unroll
    for (int i = 0; i < 4; i++) {
        float inv = 1.0f / lrow[i];
        float ov[8];
#pragma unroll
        for (int j = 0; j < 4; j++) {
            float lo, hi; unpack2(O2[i][j], lo, hi);
            ov[2 * j] = lo * inv; ov[2 * j + 1] = hi * inv;
        }
        float* op = Og + (size_t)(ty * 4 + i) * QD + tx * 8;
        *(float4*)op       = make_float4(ov[0], ov[1], ov[2], ov[3]);
        *(float4*)(op + 4) = make_float4(ov[4], ov[5], ov[6], ov[7]);
    }
}

// ---------------------------------------------------------------------------
extern "C" void kernel_launch(void* const* d_in, const int* in_sizes, int n_in,
                              void* d_out, int out_size)
{
    const float* x    = (const float*)d_in[0];
    // d_in[1] = cu_seqlens (equal-length segments; static like the reference)
    const float* cosT = (const float*)d_in[2];
    const float* sinT = (const float*)d_in[3];
    const float* Wq   = (const float*)d_in[4];
    const float* Wk   = (const float*)d_in[5];
    const float* Wv   = (const float*)d_in[6];
    const float* Wo   = (const float*)d_in[7];
    const float* qw   = (const float*)d_in[8];
    const float* kw   = (const float*)d_in[9];
    float* out = (float*)d_out;

    float *qp, *kp, *vp, *op;
    cudaGetSymbolAddress((void**)&qp, g_q);
    cudaGetSymbolAddress((void**)&kp, g_k);
    cudaGetSymbolAddress((void**)&vp, g_v);
    cudaGetSymbolAddress((void**)&op, g_o);

    // QKV projections
    gemm_nt<<<dim3(QD / 128, S_TOK / 128), 256>>>(x, Wq, qp, S_TOK, QD, HID);
    gemm_nt<<<dim3(KD / 128, S_TOK / 128), 256>>>(x, Wk, kp, S_TOK, KD, HID);
    gemm_nt<<<dim3(KD / 128, S_TOK / 128), 256>>>(x, Wv, vp, S_TOK, KD, HID);

    // RMSNorm + RoPE on Q and K
    int warps = S_TOK * (NH + NKV);
    norm_rope_kernel<<<(warps * 32 + 255) / 256, 256>>>(qp, kp, cosT, sinT, qw, kw);

    // Block-diagonal flash attention
    int smem = (3 * 64 * 128 + 64 * 68) * (int)sizeof(float);  // 115712 B
    cudaFuncSetAttribute(attn_kernel,
                         cudaFuncAttributeMaxDynamicSharedMemorySize, smem);
    attn_kernel<<<dim3(16, 8, 16), 256, smem>>>(qp, kp, vp, op);

    // Output projection -> d_out
    gemm_nt<<<dim3(HID / 128, S_TOK / 128), 256>>>(op, Wo, out, S_TOK, HID, QD);
}

// round 4
// speedup vs baseline: 1.6036x; 1.6036x over previous
#include <cuda_runtime.h>
#include <cuda_bf16.h>
#include <math.h>
#include <cstdint>

#define S_TOK  8192
#define HID    1024
#define NH     16
#define NKV    8
#define HD     128
#define SEGLEN 1024
#define QKVD   4096            // combined q|k|v output row
#define OD     2048            // attention output row
#define KP1    3072            // 3*1024 split-K (QKV proj)
#define KP2    6144            // 3*2048 split-K (out proj)
#define SCALE  0.08838834764831845f

typedef unsigned long long u64;
typedef unsigned int u32;
typedef __nv_bfloat16 bf16;

// ---------------- scratch (static device arrays, no runtime alloc) ----------
__device__ bf16  g_x2 [S_TOK * KP1];    // x split  [8192,3072]   hi|lo|hi
__device__ bf16  g_w2 [QKVD  * KP1];    // Wq|Wk|Wv split [4096,3072] hi|hi|lo
__device__ float g_qkv[S_TOK * QKVD];   // q|k|v fp32 [8192,4096]
__device__ float g_o  [S_TOK * OD];     // attention out fp32 [8192,2048]
__device__ bf16  g_o2 [S_TOK * KP2];    // attn out split [8192,6144] hi|lo|hi
__device__ bf16  g_wo2[HID   * KP2];    // Wo split [1024,6144] hi|hi|lo

// ---------------- small helpers --------------------------------------------
__device__ __forceinline__ u64 pack2(float a, float b) {
    u64 r; asm("mov.b64 %0,{%1,%2};" : "=l"(r) : "f"(a), "f"(b)); return r;
}
__device__ __forceinline__ void unpack2(u64 v, float& a, float& b) {
    asm("mov.b64 {%0,%1},%2;" : "=f"(a), "=f"(b) : "l"(v));
}
__device__ __forceinline__ void fma2(u64& c, u64 a, u64 b) {
    asm("fma.rn.f32x2 %0,%1,%2,%3;" : "=l"(c) : "l"(a), "l"(b), "l"(c));
}
__device__ __forceinline__ u64 mul2(u64 a, u64 b) {
    u64 r; asm("mul.rn.f32x2 %0,%1,%2;" : "=l"(r) : "l"(a), "l"(b)); return r;
}
__device__ __forceinline__ u32 s2u(const void* p) {
    u32 a; asm("{ .reg .u64 t; cvta.to.shared.u64 t,%1; cvt.u32.u64 %0,t; }"
               : "=r"(a) : "l"(p));
    return a;
}
__device__ __forceinline__ void cp16(u32 dst, const void* src) {
    asm volatile("cp.async.cg.shared.global [%0],[%1],16;" :: "r"(dst), "l"(src));
}
__device__ __forceinline__ void cp_commit() {
    asm volatile("cp.async.commit_group;" ::: "memory");
}
__device__ __forceinline__ void ldsm_x4(u32* r, u32 addr) {
    asm volatile("ldmatrix.sync.aligned.m8n8.x4.shared.b16 {%0,%1,%2,%3},[%4];"
                 : "=r"(r[0]), "=r"(r[1]), "=r"(r[2]), "=r"(r[3]) : "r"(addr));
}
__device__ __forceinline__ void mma16816(float* d, const u32* a, const u32* b) {
    asm volatile(
        "mma.sync.aligned.m16n8k16.row.col.f32.bf16.bf16.f32 "
        "{%0,%1,%2,%3},{%4,%5,%6,%7},{%8,%9},{%0,%1,%2,%3};"
        : "+f"(d[0]), "+f"(d[1]), "+f"(d[2]), "+f"(d[3])
        : "r"(a[0]), "r"(a[1]), "r"(a[2]), "r"(a[3]), "r"(b[0]), "r"(b[1]));
}

// ---------------------------------------------------------------------------
// split conversion: src fp32 [M,K] -> dst bf16 [M,3K]
//   isB=0 (A side): blocks hi | lo | hi
//   isB=1 (B side): blocks hi | hi | lo
// ---------------------------------------------------------------------------
__global__ __launch_bounds__(256) void cvt_split(
    const float* __restrict__ src, bf16* __restrict__ dst,
    int K, int isB, int total4)
{
    int i = blockIdx.x * blockDim.x + threadIdx.x;
    if (i >= total4) return;
    int perRow = K >> 2;
    int row = i / perRow;
    int c4 = (i - row * perRow) << 2;
    float4 v = *(const float4*)(src + (size_t)row * K + c4);
    float f[4] = {v.x, v.y, v.z, v.w};
    u64 hp = 0, lp = 0;
#pragma unroll
    for (int j = 0; j < 4; j++) {
        bf16 hb = __float2bfloat16(f[j]);
        bf16 lb = __float2bfloat16(f[j] - __bfloat162float(hb));
        hp |= (u64)(*(unsigned short*)&hb) << (16 * j);
        lp |= (u64)(*(unsigned short*)&lb) << (16 * j);
    }
    bf16* d = dst + (size_t)row * (3 * K) + c4;
    *(u64*)d           = hp;
    *(u64*)(d + K)     = isB ? hp : lp;
    *(u64*)(d + 2 * K) = isB ? lp : hp;
}

// ---------------------------------------------------------------------------
// mma.sync GEMM: C[M,N] fp32 = A[M,Kp] bf16 @ B[N,Kp]^T bf16 (both K-major)
// CTA 128x128, 8 warps (2Mx4N), warp 64x32, BK=64, 3-stage cp.async.
// smem per stage: A 16KB + B 16KB. XOR-swizzled 16B chunks.
// ---------------------------------------------------------------------------
#define GSTAGE 32768
#define GEMM_SMEM (3 * GSTAGE)   // 98304

__global__ __launch_bounds__(256) void gemm_mma(
    const bf16* __restrict__ A, const bf16* __restrict__ B,
    float* __restrict__ C, int N, int Kp)
{
    extern __shared__ char smc[];
    const u32 smb = s2u(smc);
    const int tid = threadIdx.x;
    const int warp = tid >> 5, lane = tid & 31;
    const int wM = warp >> 2, wN = warp & 3;
    const int m0 = blockIdx.y << 7, n0 = blockIdx.x << 7;
    const int chunks = Kp >> 6;

    const bf16* Ag = A + (size_t)m0 * Kp;
    const bf16* Bg = B + (size_t)n0 * Kp;

    float acc[4][4][4];
#pragma unroll
    for (int a = 0; a < 4; a++)
#pragma unroll
        for (int b = 0; b < 4; b++)
#pragma unroll
            for (int c = 0; c < 4; c++) acc[a][b][c] = 0.f;

    auto load_stage = [&](int st, int ch) {
        u32 sa = smb + st * GSTAGE;
        u32 sb = sa + 16384;
#pragma unroll
        for (int j = 0; j < 4; j++) {
            int q = tid + j * 256;
            int r = q >> 3, c = q & 7;
            cp16(sa + r * 128 + ((c ^ (r & 7)) << 4),
                 Ag + (size_t)r * Kp + ch * 64 + c * 8);
        }
#pragma unroll
        for (int j = 0; j < 4; j++) {
            int q = tid + j * 256;
            int r = q >> 3, c = q & 7;
            cp16(sb + r * 128 + ((c ^ (r & 7)) << 4),
                 Bg + (size_t)r * Kp + ch * 64 + c * 8);
        }
        cp_commit();
    };

    load_stage(0, 0);
    load_stage(1, 1);

    for (int i = 0; i < chunks; i++) {
        int s = i % 3;
        asm volatile("cp.async.wait_group 1;" ::: "memory");
        __syncthreads();
        if (i + 2 < chunks) load_stage((i + 2) % 3, i + 2);
        else cp_commit();    // keep per-thread group count uniform

        u32 sa = smb + s * GSTAGE;
        u32 sb = sa + 16384;
#pragma unroll
        for (int kk = 0; kk < 4; kk++) {
            u32 afr[4][4], bfr[2][4];
#pragma unroll
            for (int mt = 0; mt < 4; mt++) {
                int row = wM * 64 + mt * 16 + (lane & 15);
                int ch = kk * 2 + (lane >> 4);
                ldsm_x4(afr[mt], sa + row * 128 + ((ch ^ (row & 7)) << 4));
            }
#pragma unroll
            for (int p = 0; p < 2; p++) {
                int row = wN * 32 + p * 16 + ((lane >> 4) << 3) + (lane & 7);
                int ch = kk * 2 + ((lane >> 3) & 1);
                ldsm_x4(bfr[p], sb + row * 128 + ((ch ^ (row & 7)) << 4));
            }
#pragma unroll
            for (int mt = 0; mt < 4; mt++)
#pragma unroll
                for (int nt = 0; nt < 4; nt++)
                    mma16816(acc[mt][nt], afr[mt], &bfr[nt >> 1][(nt & 1) * 2]);
        }
    }

    // epilogue: direct fp32 stores
    int g = lane >> 2, t = lane & 3;
#pragma unroll
    for (int mt = 0; mt < 4; mt++) {
        int r0 = m0 + wM * 64 + mt * 16 + g;
#pragma unroll
        for (int nt = 0; nt < 4; nt++) {
            int cc = n0 + wN * 32 + nt * 8 + t * 2;
            *(float2*)(C + (size_t)r0 * N + cc) =
                make_float2(acc[mt][nt][0], acc[mt][nt][1]);
            *(float2*)(C + (size_t)(r0 + 8) * N + cc) =
                make_float2(acc[mt][nt][2], acc[mt][nt][3]);
        }
    }
}

// ---------------------------------------------------------------------------
// Fused RMSNorm + multimodal RoPE, in place on g_qkv (q and k slices).
// ---------------------------------------------------------------------------
__global__ __launch_bounds__(256) void norm_rope_kernel(
    float* __restrict__ qkv,
    const float* __restrict__ cosT, const float* __restrict__ sinT,
    const float* __restrict__ qw, const float* __restrict__ kw)
{
    int gw = (blockIdx.x * blockDim.x + threadIdx.x) >> 5;
    int lane = threadIdx.x & 31;
    if (gw >= S_TOK * (NH + NKV)) return;
    int s = gw / (NH + NKV);
    int h = gw - s * (NH + NKV);

    float* base; const float* w;
    if (h < NH) { base = qkv + (size_t)s * QKVD + h * HD;               w = qw; }
    else        { base = qkv + (size_t)s * QKVD + 2048 + (h - NH) * HD; w = kw; }

    float4 x = *(const float4*)(base + lane * 4);
    float ss = x.x * x.x + x.y * x.y + x.z * x.z + x.w * x.w;
#pragma unroll
    for (int m = 16; m > 0; m >>= 1) ss += __shfl_xor_sync(0xffffffffu, ss, m);
    float r = rsqrtf(ss * (1.0f / 128.0f) + 1e-6f);

    float4 wv = *(const float4*)(w + lane * 4);
    float xn0 = x.x * r * wv.x, xn1 = x.y * r * wv.y;
    float xn2 = x.z * r * wv.z, xn3 = x.w * r * wv.w;

    float p0 = __shfl_xor_sync(0xffffffffu, xn0, 16);
    float p1 = __shfl_xor_sync(0xffffffffu, xn1, 16);
    float p2 = __shfl_xor_sync(0xffffffffu, xn2, 16);
    float p3 = __shfl_xor_sync(0xffffffffu, xn3, 16);
    float sgn = (lane < 16) ? -1.0f : 1.0f;

    size_t toff = ((lane < 16) ? (size_t)0 : (size_t)S_TOK * HD)
                + (size_t)s * HD + lane * 4;
    float4 cv = *(const float4*)(cosT + toff);
    float4 sv = *(const float4*)(sinT + toff);

    float4 outv;
    outv.x = xn0 * cv.x + sgn * p0 * sv.x;
    outv.y = xn1 * cv.y + sgn * p1 * sv.y;
    outv.z = xn2 * cv.z + sgn * p2 * sv.z;
    outv.w = xn3 * cv.w + sgn * p3 * sv.w;
    *(float4*)(base + lane * 4) = outv;
}

// ---------------------------------------------------------------------------
// Flash attention (fp32, f32x2) over block-diagonal segments; reads g_qkv.
// ---------------------------------------------------------------------------
__global__ __launch_bounds__(256) void attn_kernel(
    const float* __restrict__ qkv, float* __restrict__ o)
{
    extern __shared__ float sm[];
    float* Qs = sm;             // [64][128]
    float* Ks = sm + 8192;      // [64][128]  swizzled
    float* Vs = sm + 16384;     // [64][128]
    float* Ps = sm + 24576;     // [64][68]

    const int tid = threadIdx.x;
    const int tx = tid & 15, ty = tid >> 4;
    const int qt = blockIdx.x, seg = blockIdx.y, h = blockIdx.z;
    const int hkv = h >> 1;

    const float* Qg = qkv + (size_t)(seg * SEGLEN + qt * 64) * QKVD + h * HD;
    const float* Kg = qkv + (size_t)(seg * SEGLEN) * QKVD + 2048 + hkv * HD;
    const float* Vg = qkv + (size_t)(seg * SEGLEN) * QKVD + 3072 + hkv * HD;

#pragma unroll
    for (int it = 0; it < 8; it++) {
        int idx = tid + it * 256;
        int r = idx >> 5, d4 = idx & 31;
        *(float4*)&Qs[r * 128 + (d4 << 2)] =
            *(const float4*)(Qg + (size_t)r * QKVD + (d4 << 2));
    }

    float mrow[4] = {-INFINITY, -INFINITY, -INFINITY, -INFINITY};
    float lrow[4] = {0.f, 0.f, 0.f, 0.f};
    u64 O2[4][4];
#pragma unroll
    for (int i = 0; i < 4; i++)
#pragma unroll
        for (int j = 0; j < 4; j++) O2[i][j] = 0ULL;

    for (int ck = 0; ck < SEGLEN / 64; ck++) {
        __syncthreads();
#pragma unroll
        for (int it = 0; it < 8; it++) {
            int idx = tid + it * 256;
            int c = idx >> 5, d4 = idx & 31;
            int sw = d4 ^ ((c >> 2) & 7);
            size_t goff = (size_t)(ck * 64 + c) * QKVD + (d4 << 2);
            *(float4*)&Ks[c * 128 + (sw << 2)] = *(const float4*)(Kg + goff);
            *(float4*)&Vs[c * 128 + (d4 << 2)] = *(const float4*)(Vg + goff);
        }
        __syncthreads();

        u64 sp[4][4];
#pragma unroll
        for (int i = 0; i < 4; i++)
#pragma unroll
            for (int j = 0; j < 4; j++) sp[i][j] = 0ULL;

#pragma unroll 8
        for (int kk4 = 0; kk4 < 32; kk4++) {
            int swk = (kk4 ^ (tx & 7)) << 2;
            u64 qp[4][2], kp[4][2];
#pragma unroll
            for (int i = 0; i < 4; i++) {
                const u64* qr = (const u64*)&Qs[(ty * 4 + i) * 128 + (kk4 << 2)];
                qp[i][0] = qr[0]; qp[i][1] = qr[1];
                const u64* kr = (const u64*)&Ks[(tx * 4 + i) * 128 + swk];
                kp[i][0] = kr[0]; kp[i][1] = kr[1];
            }
#pragma unroll
            for (int i = 0; i < 4; i++)
#pragma unroll
                for (int j = 0; j < 4; j++) {
                    fma2(sp[i][j], qp[i][0], kp[j][0]);
                    fma2(sp[i][j], qp[i][1], kp[j][1]);
                }
        }

        float pcur[4][4];
#pragma unroll
        for (int i = 0; i < 4; i++) {
            float best = -INFINITY;
#pragma unroll
            for (int j = 0; j < 4; j++) {
                float lo, hi; unpack2(sp[i][j], lo, hi);
                float val = (lo + hi) * SCALE;
                pcur[i][j] = val;
                best = fmaxf(best, val);
            }
#pragma unroll
            for (int msk = 8; msk > 0; msk >>= 1)
                best = fmaxf(best, __shfl_xor_sync(0xffffffffu, best, msk));

            float mnew = fmaxf(mrow[i], best);
            float alpha = __expf(mrow[i] - mnew);
            mrow[i] = mnew;
            float sum = 0.f;
#pragma unroll
            for (int j = 0; j < 4; j++) {
                float e = __expf(pcur[i][j] - mnew);
                pcur[i][j] = e;
                sum += e;
            }
#pragma unroll
            for (int msk = 8; msk > 0; msk >>= 1)
                sum += __shfl_xor_sync(0xffffffffu, sum, msk);
            lrow[i] = lrow[i] * alpha + sum;

            u64 ad = pack2(alpha, alpha);
#pragma unroll
            for (int j = 0; j < 4; j++) O2[i][j] = mul2(O2[i][j], ad);

            *(float4*)&Ps[(ty * 4 + i) * 68 + tx * 4] =
                make_float4(pcur[i][0], pcur[i][1], pcur[i][2], pcur[i][3]);
        }
        __syncthreads();

#pragma unroll 4
        for (int j4 = 0; j4 < 16; j4++) {
            float4 pv[4];
#pragma unroll
            for (int i = 0; i < 4; i++)
                pv[i] = *(const float4*)&Ps[(ty * 4 + i) * 68 + (j4 << 2)];
#pragma unroll
            for (int e = 0; e < 4; e++) {
                const u64* vr = (const u64*)&Vs[(j4 * 4 + e) * 128 + tx * 8];
                u64 v0 = vr[0], v1 = vr[1], v2 = vr[2], v3 = vr[3];
#pragma unroll
                for (int i = 0; i < 4; i++) {
                    float pe = ((const float*)&pv[i])[e];
                    u64 pd = pack2(pe, pe);
                    fma2(O2[i][0], pd, v0);
                    fma2(O2[i][1], pd, v1);
                    fma2(O2[i][2], pd, v2);
                    fma2(O2[i][3], pd, v3);
                }
            }
        }
    }

    float* Og = o + (size_t)(seg * SEGLEN + qt * 64) * OD + h * HD;
#pragma unroll
    for (int i = 0; i < 4; i++) {
        float inv = 1.0f / lrow[i];
        float ov[8];
#pragma unroll
        for (int j = 0; j < 4; j++) {
            float lo, hi; unpack2(O2[i][j], lo, hi);
            ov[2 * j] = lo * inv; ov[2 * j + 1] = hi * inv;
        }
        float* op = Og + (size_t)(ty * 4 + i) * OD + tx * 8;
        *(float4*)op       = make_float4(ov[0], ov[1], ov[2], ov[3]);
        *(float4*)(op + 4) = make_float4(ov[4], ov[5], ov[6], ov[7]);
    }
}

// ---------------------------------------------------------------------------
extern "C" void kernel_launch(void* const* d_in, const int* in_sizes, int n_in,
                              void* d_out, int out_size)
{
    const float* x    = (const float*)d_in[0];
    const float* cosT = (const float*)d_in[2];
    const float* sinT = (const float*)d_in[3];
    const float* Wq   = (const float*)d_in[4];
    const float* Wk   = (const float*)d_in[5];
    const float* Wv   = (const float*)d_in[6];
    const float* Wo   = (const float*)d_in[7];
    const float* qw   = (const float*)d_in[8];
    const float* kw   = (const float*)d_in[9];
    float* out = (float*)d_out;

    bf16 *x2, *w2, *o2, *wo2;
    float *qkv, *op;
    cudaGetSymbolAddress((void**)&x2,  g_x2);
    cudaGetSymbolAddress((void**)&w2,  g_w2);
    cudaGetSymbolAddress((void**)&qkv, g_qkv);
    cudaGetSymbolAddress((void**)&op,  g_o);
    cudaGetSymbolAddress((void**)&o2,  g_o2);
    cudaGetSymbolAddress((void**)&wo2, g_wo2);

    cudaFuncSetAttribute(gemm_mma,
        cudaFuncAttributeMaxDynamicSharedMemorySize, GEMM_SMEM);

    // split conversions (inputs + weights)
    {
        int t4 = S_TOK * HID / 4;
        cvt_split<<<(t4 + 255) / 256, 256>>>(x, x2, HID, 0, t4);
        t4 = 2048 * HID / 4;
        cvt_split<<<(t4 + 255) / 256, 256>>>(Wq, w2, HID, 1, t4);
        t4 = 1024 * HID / 4;
        cvt_split<<<(t4 + 255) / 256, 256>>>(Wk, w2 + (size_t)2048 * KP1, HID, 1, t4);
        cvt_split<<<(t4 + 255) / 256, 256>>>(Wv, w2 + (size_t)3072 * KP1, HID, 1, t4);
    }

    // fused QKV projection (tensor cores, split-bf16)
    gemm_mma<<<dim3(QKVD / 128, S_TOK / 128), 256, GEMM_SMEM>>>(x2, w2, qkv, QKVD, KP1);

    // RMSNorm + RoPE in place
    int warps = S_TOK * (NH + NKV);
    norm_rope_kernel<<<(warps * 32 + 255) / 256, 256>>>(qkv, cosT, sinT, qw, kw);

    // block-diagonal flash attention (fp32)
    int smem = (3 * 64 * 128 + 64 * 68) * (int)sizeof(float);
    cudaFuncSetAttribute(attn_kernel,
                         cudaFuncAttributeMaxDynamicSharedMemorySize, smem);
    attn_kernel<<<dim3(16, 8, 16), 256, smem>>>(qkv, op);

    // output projection (tensor cores, split-bf16)
    {
        int t4 = S_TOK * OD / 4;
        cvt_split<<<(t4 + 255) / 256, 256>>>(op, o2, OD, 0, t4);
        t4 = HID * OD / 4;
        cvt_split<<<(t4 + 255) / 256, 256>>>(Wo, wo2, OD, 1, t4);
    }
    gemm_mma<<<dim3(HID / 128, S_TOK / 128), 256, GEMM_SMEM>>>(o2, wo2, out, HID, KP2);
}

// round 5
// speedup vs baseline: 2.2231x; 1.3863x over previous
#include <cuda_runtime.h>
#include <cuda_bf16.h>
#include <math.h>
#include <cstdint>

#define S_TOK  8192
#define HID    1024
#define NH     16
#define NKV    8
#define HD     128
#define SEGLEN 1024
#define QKVD   4096            // combined q|k|v output row
#define OD     2048            // attention output row
#define KP1    3072            // 3*1024 split-K (QKV proj)
#define KP2    6144            // 3*2048 split-K (out proj)
#define SCALE  0.08838834764831845f

typedef unsigned long long u64;
typedef unsigned int u32;
typedef __nv_bfloat16 bf16;

// ---------------- scratch (static device arrays, no runtime alloc) ----------
__device__ bf16  g_x2 [S_TOK * KP1];      // x split  [8192,3072]   hi|lo|hi
__device__ bf16  g_w2 [QKVD  * KP1];      // Wq|Wk|Wv split [4096,3072] hi|hi|lo
__device__ float g_qkv[S_TOK * QKVD];     // q|k|v fp32 [8192,4096] (v used by attn)
__device__ bf16  g_qs [S_TOK * NH  * 256];// Q split bf16 [S][16][hi128|lo128]
__device__ bf16  g_ks [S_TOK * NKV * 256];// K split bf16 [S][8][hi128|lo128]
__device__ float g_o  [S_TOK * OD];       // attention out fp32 [8192,2048]
__device__ bf16  g_o2 [S_TOK * KP2];      // attn out split [8192,6144] hi|lo|hi
__device__ bf16  g_wo2[HID   * KP2];      // Wo split [1024,6144] hi|hi|lo

// ---------------- small helpers --------------------------------------------
__device__ __forceinline__ u64 pack2(float a, float b) {
    u64 r; asm("mov.b64 %0,{%1,%2};" : "=l"(r) : "f"(a), "f"(b)); return r;
}
__device__ __forceinline__ void unpack2(u64 v, float& a, float& b) {
    asm("mov.b64 {%0,%1},%2;" : "=f"(a), "=f"(b) : "l"(v));
}
__device__ __forceinline__ void fma2(u64& c, u64 a, u64 b) {
    asm("fma.rn.f32x2 %0,%1,%2,%3;" : "=l"(c) : "l"(a), "l"(b), "l"(c));
}
__device__ __forceinline__ u64 mul2(u64 a, u64 b) {
    u64 r; asm("mul.rn.f32x2 %0,%1,%2;" : "=l"(r) : "l"(a), "l"(b)); return r;
}
__device__ __forceinline__ u32 s2u(const void* p) {
    u32 a; asm("{ .reg .u64 t; cvta.to.shared.u64 t,%1; cvt.u32.u64 %0,t; }"
               : "=r"(a) : "l"(p));
    return a;
}
__device__ __forceinline__ void cp16(u32 dst, const void* src) {
    asm volatile("cp.async.cg.shared.global [%0],[%1],16;" :: "r"(dst), "l"(src));
}
__device__ __forceinline__ void cp_commit() {
    asm volatile("cp.async.commit_group;" ::: "memory");
}
__device__ __forceinline__ void ldsm_x4(u32* r, u32 addr) {
    asm volatile("ldmatrix.sync.aligned.m8n8.x4.shared.b16 {%0,%1,%2,%3},[%4];"
                 : "=r"(r[0]), "=r"(r[1]), "=r"(r[2]), "=r"(r[3]) : "r"(addr));
}
__device__ __forceinline__ void mma16816(float* d, const u32* a, const u32* b) {
    asm volatile(
        "mma.sync.aligned.m16n8k16.row.col.f32.bf16.bf16.f32 "
        "{%0,%1,%2,%3},{%4,%5,%6,%7},{%8,%9},{%0,%1,%2,%3};"
        : "+f"(d[0]), "+f"(d[1]), "+f"(d[2]), "+f"(d[3])
        : "r"(a[0]), "r"(a[1]), "r"(a[2]), "r"(a[3]), "r"(b[0]), "r"(b[1]));
}

// ---------------------------------------------------------------------------
// split conversion: src fp32 [M,K] -> dst bf16 [M,3K]
// ---------------------------------------------------------------------------
__global__ __launch_bounds__(256) void cvt_split(
    const float* __restrict__ src, bf16* __restrict__ dst,
    int K, int isB, int total4)
{
    int i = blockIdx.x * blockDim.x + threadIdx.x;
    if (i >= total4) return;
    int perRow = K >> 2;
    int row = i / perRow;
    int c4 = (i - row * perRow) << 2;
    float4 v = *(const float4*)(src + (size_t)row * K + c4);
    float f[4] = {v.x, v.y, v.z, v.w};
    u64 hp = 0, lp = 0;
#pragma unroll
    for (int j = 0; j < 4; j++) {
        bf16 hb = __float2bfloat16(f[j]);
        bf16 lb = __float2bfloat16(f[j] - __bfloat162float(hb));
        hp |= (u64)(*(unsigned short*)&hb) << (16 * j);
        lp |= (u64)(*(unsigned short*)&lb) << (16 * j);
    }
    bf16* d = dst + (size_t)row * (3 * K) + c4;
    *(u64*)d           = hp;
    *(u64*)(d + K)     = isB ? hp : lp;
    *(u64*)(d + 2 * K) = isB ? lp : hp;
}

// ---------------------------------------------------------------------------
// mma.sync GEMM (proven in R4): C[M,N] fp32 = A[M,Kp] bf16 @ B[N,Kp]^T bf16
// ---------------------------------------------------------------------------
#define GSTAGE 32768
#define GEMM_SMEM (3 * GSTAGE)   // 98304

__global__ __launch_bounds__(256) void gemm_mma(
    const bf16* __restrict__ A, const bf16* __restrict__ B,
    float* __restrict__ C, int N, int Kp)
{
    extern __shared__ char smc[];
    const u32 smb = s2u(smc);
    const int tid = threadIdx.x;
    const int warp = tid >> 5, lane = tid & 31;
    const int wM = warp >> 2, wN = warp & 3;
    const int m0 = blockIdx.y << 7, n0 = blockIdx.x << 7;
    const int chunks = Kp >> 6;

    const bf16* Ag = A + (size_t)m0 * Kp;
    const bf16* Bg = B + (size_t)n0 * Kp;

    float acc[4][4][4];
#pragma unroll
    for (int a = 0; a < 4; a++)
#pragma unroll
        for (int b = 0; b < 4; b++)
#pragma unroll
            for (int c = 0; c < 4; c++) acc[a][b][c] = 0.f;

    auto load_stage = [&](int st, int ch) {
        u32 sa = smb + st * GSTAGE;
        u32 sb = sa + 16384;
#pragma unroll
        for (int j = 0; j < 4; j++) {
            int q = tid + j * 256;
            int r = q >> 3, c = q & 7;
            cp16(sa + r * 128 + ((c ^ (r & 7)) << 4),
                 Ag + (size_t)r * Kp + ch * 64 + c * 8);
        }
#pragma unroll
        for (int j = 0; j < 4; j++) {
            int q = tid + j * 256;
            int r = q >> 3, c = q & 7;
            cp16(sb + r * 128 + ((c ^ (r & 7)) << 4),
                 Bg + (size_t)r * Kp + ch * 64 + c * 8);
        }
        cp_commit();
    };

    load_stage(0, 0);
    load_stage(1, 1);

    for (int i = 0; i < chunks; i++) {
        int s = i % 3;
        asm volatile("cp.async.wait_group 1;" ::: "memory");
        __syncthreads();
        if (i + 2 < chunks) load_stage((i + 2) % 3, i + 2);
        else cp_commit();

        u32 sa = smb + s * GSTAGE;
        u32 sb = sa + 16384;
#pragma unroll
        for (int kk = 0; kk < 4; kk++) {
            u32 afr[4][4], bfr[2][4];
#pragma unroll
            for (int mt = 0; mt < 4; mt++) {
                int row = wM * 64 + mt * 16 + (lane & 15);
                int ch = kk * 2 + (lane >> 4);
                ldsm_x4(afr[mt], sa + row * 128 + ((ch ^ (row & 7)) << 4));
            }
#pragma unroll
            for (int p = 0; p < 2; p++) {
                int row = wN * 32 + p * 16 + ((lane >> 4) << 3) + (lane & 7);
                int ch = kk * 2 + ((lane >> 3) & 1);
                ldsm_x4(bfr[p], sb + row * 128 + ((ch ^ (row & 7)) << 4));
            }
#pragma unroll
            for (int mt = 0; mt < 4; mt++)
#pragma unroll
                for (int nt = 0; nt < 4; nt++)
                    mma16816(acc[mt][nt], afr[mt], &bfr[nt >> 1][(nt & 1) * 2]);
        }
    }

    int g = lane >> 2, t = lane & 3;
#pragma unroll
    for (int mt = 0; mt < 4; mt++) {
        int r0 = m0 + wM * 64 + mt * 16 + g;
#pragma unroll
        for (int nt = 0; nt < 4; nt++) {
            int cc = n0 + wN * 32 + nt * 8 + t * 2;
            *(float2*)(C + (size_t)r0 * N + cc) =
                make_float2(acc[mt][nt][0], acc[mt][nt][1]);
            *(float2*)(C + (size_t)(r0 + 8) * N + cc) =
                make_float2(acc[mt][nt][2], acc[mt][nt][3]);
        }
    }
}

// ---------------------------------------------------------------------------
// RMSNorm + multimodal RoPE; reads q,k from g_qkv; writes SPLIT bf16 Q,K.
// ---------------------------------------------------------------------------
__global__ __launch_bounds__(256) void norm_rope_kernel(
    const float* __restrict__ qkv, bf16* __restrict__ qsp, bf16* __restrict__ ksp,
    const float* __restrict__ cosT, const float* __restrict__ sinT,
    const float* __restrict__ qw, const float* __restrict__ kw)
{
    int gw = (blockIdx.x * blockDim.x + threadIdx.x) >> 5;
    int lane = threadIdx.x & 31;
    if (gw >= S_TOK * (NH + NKV)) return;
    int s = gw / (NH + NKV);
    int h = gw - s * (NH + NKV);

    const float* base; const float* w; bf16* dst;
    if (h < NH) {
        base = qkv + (size_t)s * QKVD + h * HD;               w = qw;
        dst = qsp + ((size_t)s * NH + h) * 256;
    } else {
        base = qkv + (size_t)s * QKVD + 2048 + (h - NH) * HD; w = kw;
        dst = ksp + ((size_t)s * NKV + (h - NH)) * 256;
    }

    float4 x = *(const float4*)(base + lane * 4);
    float ss = x.x * x.x + x.y * x.y + x.z * x.z + x.w * x.w;
#pragma unroll
    for (int m = 16; m > 0; m >>= 1) ss += __shfl_xor_sync(0xffffffffu, ss, m);
    float r = rsqrtf(ss * (1.0f / 128.0f) + 1e-6f);

    float4 wv = *(const float4*)(w + lane * 4);
    float xn0 = x.x * r * wv.x, xn1 = x.y * r * wv.y;
    float xn2 = x.z * r * wv.z, xn3 = x.w * r * wv.w;

    float p0 = __shfl_xor_sync(0xffffffffu, xn0, 16);
    float p1 = __shfl_xor_sync(0xffffffffu, xn1, 16);
    float p2 = __shfl_xor_sync(0xffffffffu, xn2, 16);
    float p3 = __shfl_xor_sync(0xffffffffu, xn3, 16);
    float sgn = (lane < 16) ? -1.0f : 1.0f;

    size_t toff = ((lane < 16) ? (size_t)0 : (size_t)S_TOK * HD)
                + (size_t)s * HD + lane * 4;
    float4 cv = *(const float4*)(cosT + toff);
    float4 sv = *(const float4*)(sinT + toff);

    float ov[4];
    ov[0] = xn0 * cv.x + sgn * p0 * sv.x;
    ov[1] = xn1 * cv.y + sgn * p1 * sv.y;
    ov[2] = xn2 * cv.z + sgn * p2 * sv.z;
    ov[3] = xn3 * cv.w + sgn * p3 * sv.w;

    u64 hp = 0, lp = 0;
#pragma unroll
    for (int j = 0; j < 4; j++) {
        bf16 hb = __float2bfloat16(ov[j]);
        bf16 lb = __float2bfloat16(ov[j] - __bfloat162float(hb));
        hp |= (u64)(*(unsigned short*)&hb) << (16 * j);
        lp |= (u64)(*(unsigned short*)&lb) << (16 * j);
    }
    *(u64*)(dst + lane * 4)       = hp;
    *(u64*)(dst + 128 + lane * 4) = lp;
}

// ---------------------------------------------------------------------------
// Warp-specialized flash attention.
// 256 threads: warps 0-3 = scores (split-bf16 mma + online softmax),
//              warps 4-7 = PV (fp32 f32x2) + output.
// Tile: 64 q-rows; 16 key-chunks of 64; one __syncthreads per chunk.
// smem: Qs 32K | Ks 2x32K | Vs 2x32K | P 2x(64x68)f32 | alpha 2x64 | l 64
// ---------------------------------------------------------------------------
#define AQS 0
#define AKS 32768
#define AVS 98304
#define APF 163840
#define AAF 198656
#define ALF 199168
#define ATT_SMEM 199424

__global__ __launch_bounds__(256) void attn_tc(
    const bf16* __restrict__ qs, const bf16* __restrict__ ks,
    const float* __restrict__ qkv, float* __restrict__ o)
{
    extern __shared__ char sm[];
    const u32 smb = s2u(sm);
    float* Pf = (float*)(sm + APF);
    float* Af = (float*)(sm + AAF);
    float* Lf = (float*)(sm + ALF);

    const int tid = threadIdx.x;
    const int warp = tid >> 5, lane = tid & 31;
    const bool isS = warp < 4;
    const int qt = blockIdx.x, seg = blockIdx.y, h = blockIdx.z;
    const int hkv = h >> 1;

    const bf16* Qg = qs + ((size_t)(seg * SEGLEN + qt * 64) * NH + h) * 256;
    const bf16* Kg = ks + ((size_t)(seg * SEGLEN) * NKV + hkv) * 256;
    const float* Vg = qkv + (size_t)(seg * SEGLEN) * QKVD + 3072 + hkv * HD;

    // ---- prologue: Q (all threads), K0 (S), V0 (V) via cp.async ------------
#pragma unroll
    for (int j = 0; j < 8; j++) {
        int q = tid + j * 256;
        int r = q >> 5, c = q & 31;
        cp16(smb + AQS + r * 512 + ((c ^ (r & 7)) << 4),
             Qg + (size_t)r * (NH * 256) + c * 8);
    }
    cp_commit();
    if (isS) {
#pragma unroll
        for (int j = 0; j < 16; j++) {
            int q = tid + j * 128;
            int r = q >> 5, c = q & 31;
            cp16(smb + AKS + r * 512 + ((c ^ (r & 7)) << 4),
                 Kg + (size_t)r * (NKV * 256) + c * 8);
        }
        cp_commit();
    } else {
        int vt = tid - 128;
#pragma unroll
        for (int j = 0; j < 16; j++) {
            int q = vt + j * 128;
            int r = q >> 5, c = q & 31;
            cp16(smb + AVS + r * 512 + c * 16, Vg + (size_t)r * QKVD + c * 4);
        }
        cp_commit();
    }

    // per-thread state
    const int g = lane >> 2, t = lane & 3;
    float m0 = -INFINITY, m1 = -INFINITY, l0 = 0.f, l1 = 0.f;   // S-warps
    u64 O2[8][4];                                                // V-warps
#pragma unroll
    for (int i = 0; i < 8; i++)
#pragma unroll
        for (int j = 0; j < 4; j++) O2[i][j] = 0ULL;
    const int vt = tid - 128;
    const int tx = vt & 15, ty = vt >> 4;

    for (int it = 0; it <= 16; it++) {
        asm volatile("cp.async.wait_group 0;" ::: "memory");
        __syncthreads();

        if (isS && it < 16) {
            // prefetch next K chunk
            if (it + 1 < 16) {
                u32 kd = smb + AKS + ((it + 1) & 1) * 32768;
#pragma unroll
                for (int j = 0; j < 16; j++) {
                    int q = tid + j * 128;
                    int r = q >> 5, c = q & 31;
                    cp16(kd + r * 512 + ((c ^ (r & 7)) << 4),
                         Kg + (size_t)((it + 1) * 64 + r) * (NKV * 256) + c * 8);
                }
                cp_commit();
            }
            // ---- scores: 3-pass split-bf16 mma --------------------------------
            u32 kb = smb + AKS + (it & 1) * 32768;
            float acc[8][4];
#pragma unroll
            for (int n = 0; n < 8; n++)
#pragma unroll
                for (int c = 0; c < 4; c++) acc[n][c] = 0.f;

            const int ABASE[3] = {0, 16, 0};
            const int BBASE[3] = {0, 0, 16};
#pragma unroll
            for (int p = 0; p < 3; p++) {
#pragma unroll
                for (int k = 0; k < 8; k++) {
                    u32 afr[4], bfr[4][4];
                    int ar = warp * 16 + (lane & 15);
                    int ac = ABASE[p] + 2 * k + (lane >> 4);
                    ldsm_x4(afr, smb + AQS + ar * 512 + ((ac ^ (ar & 7)) << 4));
#pragma unroll
                    for (int pg = 0; pg < 4; pg++) {
                        int br = pg * 16 + ((lane >> 4) << 3) + (lane & 7);
                        int bc = BBASE[p] + 2 * k + ((lane >> 3) & 1);
                        ldsm_x4(bfr[pg], kb + br * 512 + ((bc ^ (br & 7)) << 4));
                    }
#pragma unroll
                    for (int nt = 0; nt < 8; nt++)
                        mma16816(acc[nt], afr, &bfr[nt >> 1][(nt & 1) * 2]);
                }
            }
            // ---- online softmax ----------------------------------------------
            float mx0 = -INFINITY, mx1 = -INFINITY;
#pragma unroll
            for (int n = 0; n < 8; n++) {
#pragma unroll
                for (int c = 0; c < 4; c++) acc[n][c] *= SCALE;
                mx0 = fmaxf(mx0, fmaxf(acc[n][0], acc[n][1]));
                mx1 = fmaxf(mx1, fmaxf(acc[n][2], acc[n][3]));
            }
            mx0 = fmaxf(mx0, __shfl_xor_sync(0xffffffffu, mx0, 1));
            mx0 = fmaxf(mx0, __shfl_xor_sync(0xffffffffu, mx0, 2));
            mx1 = fmaxf(mx1, __shfl_xor_sync(0xffffffffu, mx1, 1));
            mx1 = fmaxf(mx1, __shfl_xor_sync(0xffffffffu, mx1, 2));
            float mn0 = fmaxf(m0, mx0), mn1 = fmaxf(m1, mx1);
            float a0 = __expf(m0 - mn0), a1 = __expf(m1 - mn1);
            m0 = mn0; m1 = mn1;
            float s0 = 0.f, s1 = 0.f;
#pragma unroll
            for (int n = 0; n < 8; n++) {
                acc[n][0] = __expf(acc[n][0] - mn0); s0 += acc[n][0];
                acc[n][1] = __expf(acc[n][1] - mn0); s0 += acc[n][1];
                acc[n][2] = __expf(acc[n][2] - mn1); s1 += acc[n][2];
                acc[n][3] = __expf(acc[n][3] - mn1); s1 += acc[n][3];
            }
            s0 += __shfl_xor_sync(0xffffffffu, s0, 1);
            s0 += __shfl_xor_sync(0xffffffffu, s0, 2);
            s1 += __shfl_xor_sync(0xffffffffu, s1, 1);
            s1 += __shfl_xor_sync(0xffffffffu, s1, 2);
            l0 = l0 * a0 + s0;
            l1 = l1 * a1 + s1;

            int r0 = warp * 16 + g, r1 = r0 + 8;
            float* Pb = Pf + (it & 1) * (64 * 68);
#pragma unroll
            for (int n = 0; n < 8; n++) {
                *(float2*)&Pb[r0 * 68 + n * 8 + t * 2] = make_float2(acc[n][0], acc[n][1]);
                *(float2*)&Pb[r1 * 68 + n * 8 + t * 2] = make_float2(acc[n][2], acc[n][3]);
            }
            if (t == 0) {
                Af[(it & 1) * 64 + r0] = a0;
                Af[(it & 1) * 64 + r1] = a1;
                if (it == 15) { Lf[r0] = l0; Lf[r1] = l1; }
            }
        }

        if (!isS && it > 0) {
            int j = it - 1;
            // prefetch next V chunk
            if (it < 16) {
                u32 vd = smb + AVS + (it & 1) * 32768;
#pragma unroll
                for (int jj = 0; jj < 16; jj++) {
                    int q = vt + jj * 128;
                    int r = q >> 5, c = q & 31;
                    cp16(vd + r * 512 + c * 16,
                         Vg + (size_t)(it * 64 + r) * QKVD + c * 4);
                }
                cp_commit();
            }
            const float* Pb = Pf + (j & 1) * (64 * 68);
            const char* Vb = sm + AVS + (j & 1) * 32768;
            // rescale O by alpha
#pragma unroll
            for (int ii = 0; ii < 8; ii++) {
                float a = Af[(j & 1) * 64 + ty * 8 + ii];
                u64 ad = pack2(a, a);
#pragma unroll
                for (int c = 0; c < 4; c++) O2[ii][c] = mul2(O2[ii][c], ad);
            }
            // O += P @ V
#pragma unroll 2
            for (int j4 = 0; j4 < 16; j4++) {
                float pv[8][4];
#pragma unroll
                for (int ii = 0; ii < 8; ii++) {
                    float4 tmp = *(const float4*)&Pb[(ty * 8 + ii) * 68 + j4 * 4];
                    pv[ii][0] = tmp.x; pv[ii][1] = tmp.y;
                    pv[ii][2] = tmp.z; pv[ii][3] = tmp.w;
                }
#pragma unroll
                for (int e = 0; e < 4; e++) {
                    const u64* vr = (const u64*)(Vb + ((j4 * 4 + e) * 128 + tx * 8) * 4);
                    u64 v0 = vr[0], v1 = vr[1], v2 = vr[2], v3 = vr[3];
#pragma unroll
                    for (int ii = 0; ii < 8; ii++) {
                        u64 pd = pack2(pv[ii][e], pv[ii][e]);
                        fma2(O2[ii][0], pd, v0);
                        fma2(O2[ii][1], pd, v1);
                        fma2(O2[ii][2], pd, v2);
                        fma2(O2[ii][3], pd, v3);
                    }
                }
            }
        }
    }

    // ---- epilogue: V-group normalizes and stores ----------------------------
    if (!isS) {
#pragma unroll
        for (int ii = 0; ii < 8; ii++) {
            int row = ty * 8 + ii;
            float inv = 1.0f / Lf[row];
            float ov[8];
#pragma unroll
            for (int c = 0; c < 4; c++) {
                float lo, hi; unpack2(O2[ii][c], lo, hi);
                ov[2 * c] = lo * inv; ov[2 * c + 1] = hi * inv;
            }
            float* op = o + (size_t)(seg * SEGLEN + qt * 64 + row) * OD + h * HD + tx * 8;
            *(float4*)op       = make_float4(ov[0], ov[1], ov[2], ov[3]);
            *(float4*)(op + 4) = make_float4(ov[4], ov[5], ov[6], ov[7]);
        }
    }
}

// ---------------------------------------------------------------------------
extern "C" void kernel_launch(void* const* d_in, const int* in_sizes, int n_in,
                              void* d_out, int out_size)
{
    const float* x    = (const float*)d_in[0];
    const float* cosT = (const float*)d_in[2];
    const float* sinT = (const float*)d_in[3];
    const float* Wq   = (const float*)d_in[4];
    const float* Wk   = (const float*)d_in[5];
    const float* Wv   = (const float*)d_in[6];
    const float* Wo   = (const float*)d_in[7];
    const float* qw   = (const float*)d_in[8];
    const float* kw   = (const float*)d_in[9];
    float* out = (float*)d_out;

    bf16 *x2, *w2, *o2, *wo2, *qsp, *ksp;
    float *qkv, *op;
    cudaGetSymbolAddress((void**)&x2,  g_x2);
    cudaGetSymbolAddress((void**)&w2,  g_w2);
    cudaGetSymbolAddress((void**)&qkv, g_qkv);
    cudaGetSymbolAddress((void**)&op,  g_o);
    cudaGetSymbolAddress((void**)&o2,  g_o2);
    cudaGetSymbolAddress((void**)&wo2, g_wo2);
    cudaGetSymbolAddress((void**)&qsp, g_qs);
    cudaGetSymbolAddress((void**)&ksp, g_ks);

    cudaFuncSetAttribute(gemm_mma,
        cudaFuncAttributeMaxDynamicSharedMemorySize, GEMM_SMEM);
    cudaFuncSetAttribute(attn_tc,
        cudaFuncAttributeMaxDynamicSharedMemorySize, ATT_SMEM);

    // split conversions (inputs + weights)
    {
        int t4 = S_TOK * HID / 4;
        cvt_split<<<(t4 + 255) / 256, 256>>>(x, x2, HID, 0, t4);
        t4 = 2048 * HID / 4;
        cvt_split<<<(t4 + 255) / 256, 256>>>(Wq, w2, HID, 1, t4);
        t4 = 1024 * HID / 4;
        cvt_split<<<(t4 + 255) / 256, 256>>>(Wk, w2 + (size_t)2048 * KP1, HID, 1, t4);
        cvt_split<<<(t4 + 255) / 256, 256>>>(Wv, w2 + (size_t)3072 * KP1, HID, 1, t4);
    }

    // fused QKV projection
    gemm_mma<<<dim3(QKVD / 128, S_TOK / 128), 256, GEMM_SMEM>>>(x2, w2, qkv, QKVD, KP1);

    // RMSNorm + RoPE -> split bf16 Q,K
    int warps = S_TOK * (NH + NKV);
    norm_rope_kernel<<<(warps * 32 + 255) / 256, 256>>>(qkv, qsp, ksp, cosT, sinT, qw, kw);

    // warp-specialized tensor-core attention
    attn_tc<<<dim3(16, 8, 16), 256, ATT_SMEM>>>(qsp, ksp, qkv, op);

    // output projection
    {
        int t4 = S_TOK * OD / 4;
        cvt_split<<<(t4 + 255) / 256, 256>>>(op, o2, OD, 0, t4);
        t4 = HID * OD / 4;
        cvt_split<<<(t4 + 255) / 256, 256>>>(Wo, wo2, OD, 1, t4);
    }
    gemm_mma<<<dim3(HID / 128, S_TOK / 128), 256, GEMM_SMEM>>>(o2, wo2, out, HID, KP2);
}

// round 6
// speedup vs baseline: 2.2255x; 1.0011x over previous
#include <cuda_runtime.h>
#include <cuda_bf16.h>
#include <math.h>
#include <cstdint>

#define S_TOK  8192
#define HID    1024
#define NH     16
#define NKV    8
#define HD     128
#define SEGLEN 1024
#define QKVD   4096            // combined q|k|v output row
#define OD     2048            // attention output row
#define KP1    3072            // 3*1024 split-K (QKV proj)
#define KP2    6144            // 3*2048 split-K (out proj)
#define SCALE  0.08838834764831845f

typedef unsigned long long u64;
typedef unsigned int u32;
typedef __nv_bfloat16 bf16;

// ---------------- scratch (static device arrays, no runtime alloc) ----------
__device__ bf16  g_x2 [S_TOK * KP1];      // x split  [8192,3072]   hi|lo|hi
__device__ bf16  g_w2 [QKVD  * KP1];      // Wq|Wk|Wv split [4096,3072] hi|hi|lo
__device__ float g_qkv[S_TOK * QKVD];     // q|k|v fp32 [8192,4096] (v used by attn)
__device__ bf16  g_qs [S_TOK * NH  * 256];// Q split bf16 [S][16][hi128|lo128]
__device__ bf16  g_ks [S_TOK * NKV * 256];// K split bf16 [S][8][hi128|lo128]
__device__ float g_o  [S_TOK * OD];       // attention out fp32 [8192,2048]
__device__ bf16  g_o2 [S_TOK * KP2];      // attn out split [8192,6144] hi|lo|hi
__device__ bf16  g_wo2[HID   * KP2];      // Wo split [1024,6144] hi|hi|lo

// ---------------- small helpers --------------------------------------------
__device__ __forceinline__ u64 pack2(float a, float b) {
    u64 r; asm("mov.b64 %0,{%1,%2};" : "=l"(r) : "f"(a), "f"(b)); return r;
}
__device__ __forceinline__ void unpack2(u64 v, float& a, float& b) {
    asm("mov.b64 {%0,%1},%2;" : "=f"(a), "=f"(b) : "l"(v));
}
__device__ __forceinline__ void fma2(u64& c, u64 a, u64 b) {
    asm("fma.rn.f32x2 %0,%1,%2,%3;" : "=l"(c) : "l"(a), "l"(b), "l"(c));
}
__device__ __forceinline__ u64 mul2(u64 a, u64 b) {
    u64 r; asm("mul.rn.f32x2 %0,%1,%2;" : "=l"(r) : "l"(a), "l"(b)); return r;
}
__device__ __forceinline__ u32 s2u(const void* p) {
    u32 a; asm("{ .reg .u64 t; cvta.to.shared.u64 t,%1; cvt.u32.u64 %0,t; }"
               : "=r"(a) : "l"(p));
    return a;
}
__device__ __forceinline__ void cp16(u32 dst, const void* src) {
    asm volatile("cp.async.cg.shared.global [%0],[%1],16;" :: "r"(dst), "l"(src));
}
__device__ __forceinline__ void cp_commit() {
    asm volatile("cp.async.commit_group;" ::: "memory");
}
__device__ __forceinline__ void ldsm_x4(u32* r, u32 addr) {
    asm volatile("ldmatrix.sync.aligned.m8n8.x4.shared.b16 {%0,%1,%2,%3},[%4];"
                 : "=r"(r[0]), "=r"(r[1]), "=r"(r[2]), "=r"(r[3]) : "r"(addr));
}
__device__ __forceinline__ void mma16816(float* d, const u32* a, const u32* b) {
    asm volatile(
        "mma.sync.aligned.m16n8k16.row.col.f32.bf16.bf16.f32 "
        "{%0,%1,%2,%3},{%4,%5,%6,%7},{%8,%9},{%0,%1,%2,%3};"
        : "+f"(d[0]), "+f"(d[1]), "+f"(d[2]), "+f"(d[3])
        : "r"(a[0]), "r"(a[1]), "r"(a[2]), "r"(a[3]), "r"(b[0]), "r"(b[1]));
}

// ---------------------------------------------------------------------------
// split conversion: src fp32 [M,K] -> dst bf16 [M,3K]
// ---------------------------------------------------------------------------
__global__ __launch_bounds__(256) void cvt_split(
    const float* __restrict__ src, bf16* __restrict__ dst,
    int K, int isB, int total4)
{
    int i = blockIdx.x * blockDim.x + threadIdx.x;
    if (i >= total4) return;
    int perRow = K >> 2;
    int row = i / perRow;
    int c4 = (i - row * perRow) << 2;
    float4 v = *(const float4*)(src + (size_t)row * K + c4);
    float f[4] = {v.x, v.y, v.z, v.w};
    u64 hp = 0, lp = 0;
#pragma unroll
    for (int j = 0; j < 4; j++) {
        bf16 hb = __float2bfloat16(f[j]);
        bf16 lb = __float2bfloat16(f[j] - __bfloat162float(hb));
        hp |= (u64)(*(unsigned short*)&hb) << (16 * j);
        lp |= (u64)(*(unsigned short*)&lb) << (16 * j);
    }
    bf16* d = dst + (size_t)row * (3 * K) + c4;
    *(u64*)d           = hp;
    *(u64*)(d + K)     = isB ? hp : lp;
    *(u64*)(d + 2 * K) = isB ? lp : hp;
}

// ---------------------------------------------------------------------------
// mma.sync GEMM (proven in R4): C[M,N] fp32 = A[M,Kp] bf16 @ B[N,Kp]^T bf16
// ---------------------------------------------------------------------------
#define GSTAGE 32768
#define GEMM_SMEM (3 * GSTAGE)   // 98304

__global__ __launch_bounds__(256) void gemm_mma(
    const bf16* __restrict__ A, const bf16* __restrict__ B,
    float* __restrict__ C, int N, int Kp)
{
    extern __shared__ char smc[];
    const u32 smb = s2u(smc);
    const int tid = threadIdx.x;
    const int warp = tid >> 5, lane = tid & 31;
    const int wM = warp >> 2, wN = warp & 3;
    const int m0 = blockIdx.y << 7, n0 = blockIdx.x << 7;
    const int chunks = Kp >> 6;

    const bf16* Ag = A + (size_t)m0 * Kp;
    const bf16* Bg = B + (size_t)n0 * Kp;

    float acc[4][4][4];
#pragma unroll
    for (int a = 0; a < 4; a++)
#pragma unroll
        for (int b = 0; b < 4; b++)
#pragma unroll
            for (int c = 0; c < 4; c++) acc[a][b][c] = 0.f;

    auto load_stage = [&](int st, int ch) {
        u32 sa = smb + st * GSTAGE;
        u32 sb = sa + 16384;
#pragma unroll
        for (int j = 0; j < 4; j++) {
            int q = tid + j * 256;
            int r = q >> 3, c = q & 7;
            cp16(sa + r * 128 + ((c ^ (r & 7)) << 4),
                 Ag + (size_t)r * Kp + ch * 64 + c * 8);
        }
#pragma unroll
        for (int j = 0; j < 4; j++) {
            int q = tid + j * 256;
            int r = q >> 3, c = q & 7;
            cp16(sb + r * 128 + ((c ^ (r & 7)) << 4),
                 Bg + (size_t)r * Kp + ch * 64 + c * 8);
        }
        cp_commit();
    };

    load_stage(0, 0);
    load_stage(1, 1);

    for (int i = 0; i < chunks; i++) {
        int s = i % 3;
        asm volatile("cp.async.wait_group 1;" ::: "memory");
        __syncthreads();
        if (i + 2 < chunks) load_stage((i + 2) % 3, i + 2);
        else cp_commit();

        u32 sa = smb + s * GSTAGE;
        u32 sb = sa + 16384;
#pragma unroll
        for (int kk = 0; kk < 4; kk++) {
            u32 afr[4][4], bfr[2][4];
#pragma unroll
            for (int mt = 0; mt < 4; mt++) {
                int row = wM * 64 + mt * 16 + (lane & 15);
                int ch = kk * 2 + (lane >> 4);
                ldsm_x4(afr[mt], sa + row * 128 + ((ch ^ (row & 7)) << 4));
            }
#pragma unroll
            for (int p = 0; p < 2; p++) {
                int row = wN * 32 + p * 16 + ((lane >> 4) << 3) + (lane & 7);
                int ch = kk * 2 + ((lane >> 3) & 1);
                ldsm_x4(bfr[p], sb + row * 128 + ((ch ^ (row & 7)) << 4));
            }
#pragma unroll
            for (int mt = 0; mt < 4; mt++)
#pragma unroll
                for (int nt = 0; nt < 4; nt++)
                    mma16816(acc[mt][nt], afr[mt], &bfr[nt >> 1][(nt & 1) * 2]);
        }
    }

    int g = lane >> 2, t = lane & 3;
#pragma unroll
    for (int mt = 0; mt < 4; mt++) {
        int r0 = m0 + wM * 64 + mt * 16 + g;
#pragma unroll
        for (int nt = 0; nt < 4; nt++) {
            int cc = n0 + wN * 32 + nt * 8 + t * 2;
            *(float2*)(C + (size_t)r0 * N + cc) =
                make_float2(acc[mt][nt][0], acc[mt][nt][1]);
            *(float2*)(C + (size_t)(r0 + 8) * N + cc) =
                make_float2(acc[mt][nt][2], acc[mt][nt][3]);
        }
    }
}

// ---------------------------------------------------------------------------
// RMSNorm + multimodal RoPE; reads q,k from g_qkv; writes SPLIT bf16 Q,K.
// ---------------------------------------------------------------------------
__global__ __launch_bounds__(256) void norm_rope_kernel(
    const float* __restrict__ qkv, bf16* __restrict__ qsp, bf16* __restrict__ ksp,
    const float* __restrict__ cosT, const float* __restrict__ sinT,
    const float* __restrict__ qw, const float* __restrict__ kw)
{
    int gw = (blockIdx.x * blockDim.x + threadIdx.x) >> 5;
    int lane = threadIdx.x & 31;
    if (gw >= S_TOK * (NH + NKV)) return;
    int s = gw / (NH + NKV);
    int h = gw - s * (NH + NKV);

    const float* base; const float* w; bf16* dst;
    if (h < NH) {
        base = qkv + (size_t)s * QKVD + h * HD;               w = qw;
        dst = qsp + ((size_t)s * NH + h) * 256;
    } else {
        base = qkv + (size_t)s * QKVD + 2048 + (h - NH) * HD; w = kw;
        dst = ksp + ((size_t)s * NKV + (h - NH)) * 256;
    }

    float4 x = *(const float4*)(base + lane * 4);
    float ss = x.x * x.x + x.y * x.y + x.z * x.z + x.w * x.w;
#pragma unroll
    for (int m = 16; m > 0; m >>= 1) ss += __shfl_xor_sync(0xffffffffu, ss, m);
    float r = rsqrtf(ss * (1.0f / 128.0f) + 1e-6f);

    float4 wv = *(const float4*)(w + lane * 4);
    float xn0 = x.x * r * wv.x, xn1 = x.y * r * wv.y;
    float xn2 = x.z * r * wv.z, xn3 = x.w * r * wv.w;

    float p0 = __shfl_xor_sync(0xffffffffu, xn0, 16);
    float p1 = __shfl_xor_sync(0xffffffffu, xn1, 16);
    float p2 = __shfl_xor_sync(0xffffffffu, xn2, 16);
    float p3 = __shfl_xor_sync(0xffffffffu, xn3, 16);
    float sgn = (lane < 16) ? -1.0f : 1.0f;

    size_t toff = ((lane < 16) ? (size_t)0 : (size_t)S_TOK * HD)
                + (size_t)s * HD + lane * 4;
    float4 cv = *(const float4*)(cosT + toff);
    float4 sv = *(const float4*)(sinT + toff);

    float ov[4];
    ov[0] = xn0 * cv.x + sgn * p0 * sv.x;
    ov[1] = xn1 * cv.y + sgn * p1 * sv.y;
    ov[2] = xn2 * cv.z + sgn * p2 * sv.z;
    ov[3] = xn3 * cv.w + sgn * p3 * sv.w;

    u64 hp = 0, lp = 0;
#pragma unroll
    for (int j = 0; j < 4; j++) {
        bf16 hb = __float2bfloat16(ov[j]);
        bf16 lb = __float2bfloat16(ov[j] - __bfloat162float(hb));
        hp |= (u64)(*(unsigned short*)&hb) << (16 * j);
        lp |= (u64)(*(unsigned short*)&lb) << (16 * j);
    }
    *(u64*)(dst + lane * 4)       = hp;
    *(u64*)(dst + 128 + lane * 4) = lp;
}

// ---------------------------------------------------------------------------
// Warp-specialized flash attention.
// 256 threads: warps 0-3 = scores (split-bf16 mma + online softmax),
//              warps 4-7 = PV (fp32 f32x2) + output.
// Tile: 64 q-rows; 16 key-chunks of 64; one __syncthreads per chunk.
// smem: Qs 32K | Ks 2x32K | Vs 2x32K | P 2x(64x68)f32 | alpha 2x64 | l 64
// ---------------------------------------------------------------------------
#define AQS 0
#define AKS 32768
#define AVS 98304
#define APF 163840
#define AAF 198656
#define ALF 199168
#define ATT_SMEM 199424

__global__ __launch_bounds__(256) void attn_tc(
    const bf16* __restrict__ qs, const bf16* __restrict__ ks,
    const float* __restrict__ qkv, float* __restrict__ o)
{
    extern __shared__ char sm[];
    const u32 smb = s2u(sm);
    float* Pf = (float*)(sm + APF);
    float* Af = (float*)(sm + AAF);
    float* Lf = (float*)(sm + ALF);

    const int tid = threadIdx.x;
    const int warp = tid >> 5, lane = tid & 31;
    const bool isS = warp < 4;
    const int qt = blockIdx.x, seg = blockIdx.y, h = blockIdx.z;
    const int hkv = h >> 1;

    const bf16* Qg = qs + ((size_t)(seg * SEGLEN + qt * 64) * NH + h) * 256;
    const bf16* Kg = ks + ((size_t)(seg * SEGLEN) * NKV + hkv) * 256;
    const float* Vg = qkv + (size_t)(seg * SEGLEN) * QKVD + 3072 + hkv * HD;

    // ---- prologue: Q (all threads), K0 (S), V0 (V) via cp.async ------------
#pragma unroll
    for (int j = 0; j < 8; j++) {
        int q = tid + j * 256;
        int r = q >> 5, c = q & 31;
        cp16(smb + AQS + r * 512 + ((c ^ (r & 7)) << 4),
             Qg + (size_t)r * (NH * 256) + c * 8);
    }
    cp_commit();
    if (isS) {
#pragma unroll
        for (int j = 0; j < 16; j++) {
            int q = tid + j * 128;
            int r = q >> 5, c = q & 31;
            cp16(smb + AKS + r * 512 + ((c ^ (r & 7)) << 4),
                 Kg + (size_t)r * (NKV * 256) + c * 8);
        }
        cp_commit();
    } else {
        int vt = tid - 128;
#pragma unroll
        for (int j = 0; j < 16; j++) {
            int q = vt + j * 128;
            int r = q >> 5, c = q & 31;
            cp16(smb + AVS + r * 512 + c * 16, Vg + (size_t)r * QKVD + c * 4);
        }
        cp_commit();
    }

    // per-thread state
    const int g = lane >> 2, t = lane & 3;
    float m0 = -INFINITY, m1 = -INFINITY, l0 = 0.f, l1 = 0.f;   // S-warps
    u64 O2[8][4];                                                // V-warps
#pragma unroll
    for (int i = 0; i < 8; i++)
#pragma unroll
        for (int j = 0; j < 4; j++) O2[i][j] = 0ULL;
    const int vt = tid - 128;
    const int tx = vt & 15, ty = vt >> 4;

    for (int it = 0; it <= 16; it++) {
        asm volatile("cp.async.wait_group 0;" ::: "memory");
        __syncthreads();

        if (isS && it < 16) {
            // prefetch next K chunk
            if (it + 1 < 16) {
                u32 kd = smb + AKS + ((it + 1) & 1) * 32768;
#pragma unroll
                for (int j = 0; j < 16; j++) {
                    int q = tid + j * 128;
                    int r = q >> 5, c = q & 31;
                    cp16(kd + r * 512 + ((c ^ (r & 7)) << 4),
                         Kg + (size_t)((it + 1) * 64 + r) * (NKV * 256) + c * 8);
                }
                cp_commit();
            }
            // ---- scores: 3-pass split-bf16 mma --------------------------------
            u32 kb = smb + AKS + (it & 1) * 32768;
            float acc[8][4];
#pragma unroll
            for (int n = 0; n < 8; n++)
#pragma unroll
                for (int c = 0; c < 4; c++) acc[n][c] = 0.f;

            const int ABASE[3] = {0, 16, 0};
            const int BBASE[3] = {0, 0, 16};
#pragma unroll
            for (int p = 0; p < 3; p++) {
#pragma unroll
                for (int k = 0; k < 8; k++) {
                    u32 afr[4], bfr[4][4];
                    int ar = warp * 16 + (lane & 15);
                    int ac = ABASE[p] + 2 * k + (lane >> 4);
                    ldsm_x4(afr, smb + AQS + ar * 512 + ((ac ^ (ar & 7)) << 4));
#pragma unroll
                    for (int pg = 0; pg < 4; pg++) {
                        int br = pg * 16 + ((lane >> 4) << 3) + (lane & 7);
                        int bc = BBASE[p] + 2 * k + ((lane >> 3) & 1);
                        ldsm_x4(bfr[pg], kb + br * 512 + ((bc ^ (br & 7)) << 4));
                    }
#pragma unroll
                    for (int nt = 0; nt < 8; nt++)
                        mma16816(acc[nt], afr, &bfr[nt >> 1][(nt & 1) * 2]);
                }
            }
            // ---- online softmax ----------------------------------------------
            float mx0 = -INFINITY, mx1 = -INFINITY;
#pragma unroll
            for (int n = 0; n < 8; n++) {
#pragma unroll
                for (int c = 0; c < 4; c++) acc[n][c] *= SCALE;
                mx0 = fmaxf(mx0, fmaxf(acc[n][0], acc[n][1]));
                mx1 = fmaxf(mx1, fmaxf(acc[n][2], acc[n][3]));
            }
            mx0 = fmaxf(mx0, __shfl_xor_sync(0xffffffffu, mx0, 1));
            mx0 = fmaxf(mx0, __shfl_xor_sync(0xffffffffu, mx0, 2));
            mx1 = fmaxf(mx1, __shfl_xor_sync(0xffffffffu, mx1, 1));
            mx1 = fmaxf(mx1, __shfl_xor_sync(0xffffffffu, mx1, 2));
            float mn0 = fmaxf(m0, mx0), mn1 = fmaxf(m1, mx1);
            float a0 = __expf(m0 - mn0), a1 = __expf(m1 - mn1);
            m0 = mn0; m1 = mn1;
            float s0 = 0.f, s1 = 0.f;
#pragma unroll
            for (int n = 0; n < 8; n++) {
                acc[n][0] = __expf(acc[n][0] - mn0); s0 += acc[n][0];
                acc[n][1] = __expf(acc[n][1] - mn0); s0 += acc[n][1];
                acc[n][2] = __expf(acc[n][2] - mn1); s1 += acc[n][2];
                acc[n][3] = __expf(acc[n][3] - mn1); s1 += acc[n][3];
            }
            s0 += __shfl_xor_sync(0xffffffffu, s0, 1);
            s0 += __shfl_xor_sync(0xffffffffu, s0, 2);
            s1 += __shfl_xor_sync(0xffffffffu, s1, 1);
            s1 += __shfl_xor_sync(0xffffffffu, s1, 2);
            l0 = l0 * a0 + s0;
            l1 = l1 * a1 + s1;

            int r0 = warp * 16 + g, r1 = r0 + 8;
            float* Pb = Pf + (it & 1) * (64 * 68);
#pragma unroll
            for (int n = 0; n < 8; n++) {
                *(float2*)&Pb[r0 * 68 + n * 8 + t * 2] = make_float2(acc[n][0], acc[n][1]);
                *(float2*)&Pb[r1 * 68 + n * 8 + t * 2] = make_float2(acc[n][2], acc[n][3]);
            }
            if (t == 0) {
                Af[(it & 1) * 64 + r0] = a0;
                Af[(it & 1) * 64 + r1] = a1;
                if (it == 15) { Lf[r0] = l0; Lf[r1] = l1; }
            }
        }

        if (!isS && it > 0) {
            int j = it - 1;
            // prefetch next V chunk
            if (it < 16) {
                u32 vd = smb + AVS + (it & 1) * 32768;
#pragma unroll
                for (int jj = 0; jj < 16; jj++) {
                    int q = vt + jj * 128;
                    int r = q >> 5, c = q & 31;
                    cp16(vd + r * 512 + c * 16,
                         Vg + (size_t)(it * 64 + r) * QKVD + c * 4);
                }
                cp_commit();
            }
            const float* Pb = Pf + (j & 1) * (64 * 68);
            const char* Vb = sm + AVS + (j & 1) * 32768;
            // rescale O by alpha
#pragma unroll
            for (int ii = 0; ii < 8; ii++) {
                float a = Af[(j & 1) * 64 + ty * 8 + ii];
                u64 ad = pack2(a, a);
#pragma unroll
                for (int c = 0; c < 4; c++) O2[ii][c] = mul2(O2[ii][c], ad);
            }
            // O += P @ V
#pragma unroll 2
            for (int j4 = 0; j4 < 16; j4++) {
                float pv[8][4];
#pragma unroll
                for (int ii = 0; ii < 8; ii++) {
                    float4 tmp = *(const float4*)&Pb[(ty * 8 + ii) * 68 + j4 * 4];
                    pv[ii][0] = tmp.x; pv[ii][1] = tmp.y;
                    pv[ii][2] = tmp.z; pv[ii][3] = tmp.w;
                }
#pragma unroll
                for (int e = 0; e < 4; e++) {
                    const u64* vr = (const u64*)(Vb + ((j4 * 4 + e) * 128 + tx * 8) * 4);
                    u64 v0 = vr[0], v1 = vr[1], v2 = vr[2], v3 = vr[3];
#pragma unroll
                    for (int ii = 0; ii < 8; ii++) {
                        u64 pd = pack2(pv[ii][e], pv[ii][e]);
                        fma2(O2[ii][0], pd, v0);
                        fma2(O2[ii][1], pd, v1);
                        fma2(O2[ii][2], pd, v2);
                        fma2(O2[ii][3], pd, v3);
                    }
                }
            }
        }
    }

    // ---- epilogue: V-group normalizes and stores ----------------------------
    if (!isS) {
#pragma unroll
        for (int ii = 0; ii < 8; ii++) {
            int row = ty * 8 + ii;
            float inv = 1.0f / Lf[row];
            float ov[8];
#pragma unroll
            for (int c = 0; c < 4; c++) {
                float lo, hi; unpack2(O2[ii][c], lo, hi);
                ov[2 * c] = lo * inv; ov[2 * c + 1] = hi * inv;
            }
            float* op = o + (size_t)(seg * SEGLEN + qt * 64 + row) * OD + h * HD + tx * 8;
            *(float4*)op       = make_float4(ov[0], ov[1], ov[2], ov[3]);
            *(float4*)(op + 4) = make_float4(ov[4], ov[5], ov[6], ov[7]);
        }
    }
}

// ---------------------------------------------------------------------------
extern "C" void kernel_launch(void* const* d_in, const int* in_sizes, int n_in,
                              void* d_out, int out_size)
{
    const float* x    = (const float*)d_in[0];
    const float* cosT = (const float*)d_in[2];
    const float* sinT = (const float*)d_in[3];
    const float* Wq   = (const float*)d_in[4];
    const float* Wk   = (const float*)d_in[5];
    const float* Wv   = (const float*)d_in[6];
    const float* Wo   = (const float*)d_in[7];
    const float* qw   = (const float*)d_in[8];
    const float* kw   = (const float*)d_in[9];
    float* out = (float*)d_out;

    bf16 *x2, *w2, *o2, *wo2, *qsp, *ksp;
    float *qkv, *op;
    cudaGetSymbolAddress((void**)&x2,  g_x2);
    cudaGetSymbolAddress((void**)&w2,  g_w2);
    cudaGetSymbolAddress((void**)&qkv, g_qkv);
    cudaGetSymbolAddress((void**)&op,  g_o);
    cudaGetSymbolAddress((void**)&o2,  g_o2);
    cudaGetSymbolAddress((void**)&wo2, g_wo2);
    cudaGetSymbolAddress((void**)&qsp, g_qs);
    cudaGetSymbolAddress((void**)&ksp, g_ks);

    cudaFuncSetAttribute(gemm_mma,
        cudaFuncAttributeMaxDynamicSharedMemorySize, GEMM_SMEM);
    cudaFuncSetAttribute(attn_tc,
        cudaFuncAttributeMaxDynamicSharedMemorySize, ATT_SMEM);

    // split conversions (inputs + weights)
    {
        int t4 = S_TOK * HID / 4;
        cvt_split<<<(t4 + 255) / 256, 256>>>(x, x2, HID, 0, t4);
        t4 = 2048 * HID / 4;
        cvt_split<<<(t4 + 255) / 256, 256>>>(Wq, w2, HID, 1, t4);
        t4 = 1024 * HID / 4;
        cvt_split<<<(t4 + 255) / 256, 256>>>(Wk, w2 + (size_t)2048 * KP1, HID, 1, t4);
        cvt_split<<<(t4 + 255) / 256, 256>>>(Wv, w2 + (size_t)3072 * KP1, HID, 1, t4);
    }

    // fused QKV projection
    gemm_mma<<<dim3(QKVD / 128, S_TOK / 128), 256, GEMM_SMEM>>>(x2, w2, qkv, QKVD, KP1);

    // RMSNorm + RoPE -> split bf16 Q,K
    int warps = S_TOK * (NH + NKV);
    norm_rope_kernel<<<(warps * 32 + 255) / 256, 256>>>(qkv, qsp, ksp, cosT, sinT, qw, kw);

    // warp-specialized tensor-core attention
    attn_tc<<<dim3(16, 8, 16), 256, ATT_SMEM>>>(qsp, ksp, qkv, op);

    // output projection
    {
        int t4 = S_TOK * OD / 4;
        cvt_split<<<(t4 + 255) / 256, 256>>>(op, o2, OD, 0, t4);
        t4 = HID * OD / 4;
        cvt_split<<<(t4 + 255) / 256, 256>>>(Wo, wo2, OD, 1, t4);
    }
    gemm_mma<<<dim3(HID / 128, S_TOK / 128), 256, GEMM_SMEM>>>(o2, wo2, out, HID, KP2);
}